// round 12
// baseline (speedup 1.0000x reference)
#include <cuda_runtime.h>

#define B_ 2
#define N_ 16384
#define S_ 4096
#define K_ 32
#define C0 67
#define C1 64
#define C2 64
#define C3 128
#define ST 36
#define FULLM 0xffffffffu
#define FINF 3.402823466e38f

typedef unsigned long long ull;

__device__ __forceinline__ ull fma2(ull a, ull b, ull c){
    ull d;
    asm("fma.rn.f32x2 %0, %1, %2, %3;" : "=l"(d) : "l"(a), "l"(b), "l"(c));
    return d;
}
__device__ __forceinline__ ull mul2(ull a, ull b){
    ull d;
    asm("mul.rn.f32x2 %0, %1, %2;" : "=l"(d) : "l"(a), "l"(b));
    return d;
}
__device__ __forceinline__ ull pk(float lo, float hi){
    ull r; asm("mov.b64 %0, {%1,%2};" : "=l"(r) : "f"(lo), "f"(hi)); return r;
}
__device__ __forceinline__ float2 upk(ull v){
    float2 f; asm("mov.b64 {%0,%1}, %2;" : "=f"(f.x), "=f"(f.y) : "l"(v)); return f;
}

// ---------------- scratch ----------------
__device__ __align__(16) float  d_pt[B_*N_*C1];
__device__ __align__(16) float4 d_xyz4[B_*N_];
__device__              int     d_knn[B_*S_*K_];
__device__ __align__(16) float  d_buf0[(size_t)B_*S_*C1*K_];
__device__ __align__(16) float  d_buf1[(size_t)B_*S_*C2*K_];
__device__              float   d_maxb[B_*S_*C3];
__device__              float   d_minb[B_*S_*C3];
__device__              float   d_ps0[4096*C1], d_pq0[4096*C1];
__device__              float   d_ps1[4096*C2], d_pq1[4096*C2];
__device__              float   d_ps2[8192*C3], d_pq2[8192*C3];
__device__              float   d_mean0[C1], d_istd0[C1];
__device__              float   d_mean1[C2], d_istd1[C2];
__device__              float   d_mean2[C3], d_istd2[C3];

// ---------------- transpose points (split-capable) ----------------
__global__ void k_tr(const float* __restrict__ pts, int xoff){
    __shared__ float tile[32][33];
    int b = blockIdx.z, c0 = blockIdx.y*32, n0 = (blockIdx.x + xoff)*32;
    for (int j = threadIdx.y; j < 32; j += 8)
        tile[j][threadIdx.x] = pts[((size_t)(b*C1 + c0 + j))*N_ + n0 + threadIdx.x];
    __syncthreads();
    for (int j = threadIdx.y; j < 32; j += 8)
        d_pt[((size_t)(b*N_ + n0 + j))*C1 + c0 + threadIdx.x] = tile[threadIdx.x][j];
}

// ---------------- xyz4 + new_xyz ----------------
__global__ void k_xyz(const float* __restrict__ xyz, float* __restrict__ out){
    int i = blockIdx.x*blockDim.x + threadIdx.x;
    if (i >= B_*N_) return;
    int b = i / N_, n = i % N_;
    float x = xyz[(b*3+0)*N_+n], y = xyz[(b*3+1)*N_+n], z = xyz[(b*3+2)*N_+n];
    d_xyz4[i] = make_float4(x, y, z, fmaf(z,z, fmaf(y,y, x*x)));
    if (n < S_){
        out[(b*3+0)*S_+n] = x;
        out[(b*3+1)*S_+n] = y;
        out[(b*3+2)*S_+n] = z;
    }
}

// ---------------- KNN: 2 q/warp; SoA packed f32x2; lexicographic (d,idx) top-32 ----------------
__device__ __forceinline__ void knn_ins(float d, int idx, int lane,
                                        float& bd, int& bi, float& cm){
    unsigned m = __ballot_sync(FULLM, d <= cm);
    if (m){
        do {
            int src = __ffs(m) - 1; m &= m - 1;
            float cd = __shfl_sync(FULLM, d, src);
            int   cn = __shfl_sync(FULLM, idx, src);
            float pd = __shfl_up_sync(FULLM, bd, 1);
            int   pi = __shfl_up_sync(FULLM, bi, 1);
            if (lane == 0){ pd = -FINF; pi = -1; }
            bool shift = (bd > cd) || (bd == cd && bi > cn);
            if (shift){
                bool f = (pd < cd) || (pd == cd && pi <= cn);
                bd = f ? cd : pd;
                bi = f ? cn : pi;
            }
        } while (m);
        cm = __shfl_sync(FULLM, bd, 31);
    }
}

__global__ void __launch_bounds__(128) k_knn(){
    __shared__ float sxs[2][512], sys[2][512], szs[2][512], sws[2][512];
    int t = threadIdx.x;
    int lane = t & 31, w = t >> 5;
    int qg0 = (blockIdx.x*4 + w)*2;
    int b = qg0 >> 12;
    int s0 = qg0 & (S_ - 1);
    const float4* base = &d_xyz4[b*N_];
    float4 cA = base[s0], cB = base[s0 + 1];
    ull ax2 = pk(cA.x,cA.x), ay2 = pk(cA.y,cA.y), az2 = pk(cA.z,cA.z);
    ull bx2 = pk(cB.x,cB.x), by2 = pk(cB.y,cB.y), bz2 = pk(cB.z,cB.z);
    ull neg2 = pk(-2.0f,-2.0f);

    float bd0 = FINF, bd1 = FINF;
    int   bi0 = 0,    bi1 = 0;
    float cm0 = FINF, cm1 = FINF;

    // preload tile 0 (SoA)
    #pragma unroll
    for (int i = 0; i < 4; i++){
        int ii = t + 128*i;
        float4 v = base[ii];
        sxs[0][ii] = v.x; sys[0][ii] = v.y; szs[0][ii] = v.z; sws[0][ii] = v.w;
    }
    __syncthreads();

    int cur = 0;
    for (int j0 = 0; j0 < N_; j0 += 512){
        float4 pf[4];
        bool more = (j0 + 512) < N_;
        if (more){
            #pragma unroll
            for (int i = 0; i < 4; i++)
                pf[i] = base[j0 + 512 + t + 128*i];
        }

        const float* Xs = sxs[cur];
        const float* Ys = sys[cur];
        const float* Zs = szs[cur];
        const float* Ws = sws[cur];

        #pragma unroll
        for (int c = 0; c < 2; c++){
            int cb = c*256;
            ulonglong2 xlo = *(const ulonglong2*)(Xs + cb + lane*4);
            ulonglong2 xhi = *(const ulonglong2*)(Xs + cb + 128 + lane*4);
            ulonglong2 ylo = *(const ulonglong2*)(Ys + cb + lane*4);
            ulonglong2 yhi = *(const ulonglong2*)(Ys + cb + 128 + lane*4);
            ulonglong2 zlo = *(const ulonglong2*)(Zs + cb + lane*4);
            ulonglong2 zhi = *(const ulonglong2*)(Zs + cb + 128 + lane*4);
            ulonglong2 wlo = *(const ulonglong2*)(Ws + cb + lane*4);
            ulonglong2 whi = *(const ulonglong2*)(Ws + cb + 128 + lane*4);
            ull xp[4] = {xlo.x, xlo.y, xhi.x, xhi.y};
            ull yp[4] = {ylo.x, ylo.y, yhi.x, yhi.y};
            ull zp[4] = {zlo.x, zlo.y, zhi.x, zhi.y};
            ull wp[4] = {wlo.x, wlo.y, whi.x, whi.y};

            float fA[8], fB[8];
            #pragma unroll
            for (int p = 0; p < 4; p++){
                ull dotA = fma2(az2, zp[p], fma2(ay2, yp[p], mul2(ax2, xp[p])));
                ull dA = fma2(dotA, neg2, wp[p]);
                ull dotB = fma2(bz2, zp[p], fma2(by2, yp[p], mul2(bx2, xp[p])));
                ull dB = fma2(dotB, neg2, wp[p]);
                float2 uA = upk(dA), uB = upk(dB);
                fA[2*p] = uA.x; fA[2*p+1] = uA.y;
                fB[2*p] = uB.x; fB[2*p+1] = uB.y;
            }

            bool proc;
            if (j0 == 0){
                proc = true;
            } else {
                float mA = fminf(fminf(fminf(fA[0],fA[1]), fminf(fA[2],fA[3])),
                                 fminf(fminf(fA[4],fA[5]), fminf(fA[6],fA[7])));
                float mB = fminf(fminf(fminf(fB[0],fB[1]), fminf(fB[2],fB[3])),
                                 fminf(fminf(fB[4],fB[5]), fminf(fB[6],fB[7])));
                unsigned any = __ballot_sync(FULLM, (mA <= cm0) | (mB <= cm1));
                proc = (any != 0);
            }
            if (proc){
                #pragma unroll
                for (int l = 0; l < 8; l++){
                    // pair p = l>>1; half h = l>>2; sub q = (l>>1)&1; s = l&1
                    int idx = j0 + cb + (l>>2)*128 + 4*lane + ((l>>1)&1)*2 + (l&1);
                    knn_ins(fA[l], idx, lane, bd0, bi0, cm0);
                }
                #pragma unroll
                for (int l = 0; l < 8; l++){
                    int idx = j0 + cb + (l>>2)*128 + 4*lane + ((l>>1)&1)*2 + (l&1);
                    knn_ins(fB[l], idx, lane, bd1, bi1, cm1);
                }
            }
        }

        if (more){
            int nx = cur ^ 1;
            #pragma unroll
            for (int i = 0; i < 4; i++){
                int ii = t + 128*i;
                sxs[nx][ii] = pf[i].x; sys[nx][ii] = pf[i].y;
                szs[nx][ii] = pf[i].z; sws[nx][ii] = pf[i].w;
            }
        }
        __syncthreads();
        cur ^= 1;
    }
    d_knn[qg0*K_ + lane]     = bi0;
    d_knn[(qg0+1)*K_ + lane] = bi1;
}

// ---------------- layer0: gather + GEMM, 8x8 tile per thread, warp per point ----------------
__global__ void __launch_bounds__(128, 4) k_g0(const float* __restrict__ W0g){
    extern __shared__ float dyn[];
    float* sx = dyn;                 // 4 * C0 * ST
    float* sw = dyn + 4*C0*ST;       // C0 * 64
    __shared__ float ssum[C1], ssq[C1];
    int t = threadIdx.x;
    int bs0 = blockIdx.x*4;

    for (int e = t; e < C0*64; e += 128){
        int ci = e >> 6, co = e & 63;
        sw[e] = W0g[co*C0 + ci];
    }
    if (t < C1){ ssum[t] = 0.f; ssq[t] = 0.f; }

    { // gather: 1 thread per (point, k)
        int s_l = t >> 5, k = t & 31;
        int bs = bs0 + s_l;
        int b = bs / S_, s = bs % S_;
        int idx = d_knn[bs*K_ + k];
        float* xr = &sx[s_l*C0*ST];
        float4 pc = d_xyz4[b*N_ + s];
        float4 pn = d_xyz4[b*N_ + idx];
        xr[0*ST + k] = pn.x - pc.x;
        xr[1*ST + k] = pn.y - pc.y;
        xr[2*ST + k] = pn.z - pc.z;
        const float4* prow = (const float4*)&d_pt[((size_t)(b*N_ + idx))*C1];
        #pragma unroll
        for (int q = 0; q < 16; q++){
            float4 v = prow[q];
            int c = 3 + q*4;
            xr[(c+0)*ST + k] = v.x;
            xr[(c+1)*ST + k] = v.y;
            xr[(c+2)*ST + k] = v.z;
            xr[(c+3)*ST + k] = v.w;
        }
    }
    __syncthreads();

    int lane = t & 31, wp = t >> 5;
    int kq = lane & 3, cog = lane >> 2;
    const float* xb_ = &sx[wp*C0*ST + kq*8];
    const float* wb_ = sw + cog*8;
    ull acc[8][4];
    #pragma unroll
    for (int j = 0; j < 8; j++){ acc[j][0]=0; acc[j][1]=0; acc[j][2]=0; acc[j][3]=0; }

    for (int ci = 0; ci < C0; ci++){
        float4 xa = *(const float4*)(xb_ + ci*ST);
        float4 xc = *(const float4*)(xb_ + ci*ST + 4);
        ull x0 = pk(xa.x,xa.y), x1 = pk(xa.z,xa.w);
        ull x2 = pk(xc.x,xc.y), x3 = pk(xc.z,xc.w);
        float4 wa = *(const float4*)(wb_ + ci*64);
        float4 wc = *(const float4*)(wb_ + ci*64 + 4);
        float wv[8] = {wa.x,wa.y,wa.z,wa.w, wc.x,wc.y,wc.z,wc.w};
        #pragma unroll
        for (int j = 0; j < 8; j++){
            ull w2 = pk(wv[j], wv[j]);
            acc[j][0] = fma2(w2, x0, acc[j][0]);
            acc[j][1] = fma2(w2, x1, acc[j][1]);
            acc[j][2] = fma2(w2, x2, acc[j][2]);
            acc[j][3] = fma2(w2, x3, acc[j][3]);
        }
    }

    int bs = bs0 + wp;
    float* orow = &d_buf0[(size_t)bs*C1*K_];
    float ls[8], lq[8];
    #pragma unroll
    for (int j = 0; j < 8; j++){
        float2 a0 = upk(acc[j][0]), a1 = upk(acc[j][1]);
        float2 a2 = upk(acc[j][2]), a3 = upk(acc[j][3]);
        *(float4*)&orow[(cog*8+j)*K_ + kq*8]     = make_float4(a0.x,a0.y,a1.x,a1.y);
        *(float4*)&orow[(cog*8+j)*K_ + kq*8 + 4] = make_float4(a2.x,a2.y,a3.x,a3.y);
        ls[j] = ((a0.x+a0.y)+(a1.x+a1.y)) + ((a2.x+a2.y)+(a3.x+a3.y));
        float q0 = fmaf(a0.x,a0.x, fmaf(a0.y,a0.y, fmaf(a1.x,a1.x, a1.y*a1.y)));
        lq[j] = fmaf(a2.x,a2.x, fmaf(a2.y,a2.y, fmaf(a3.x,a3.x, fmaf(a3.y,a3.y, q0))));
    }
    #pragma unroll
    for (int j = 0; j < 8; j++){
        ls[j] += __shfl_xor_sync(FULLM, ls[j], 1);
        ls[j] += __shfl_xor_sync(FULLM, ls[j], 2);
        lq[j] += __shfl_xor_sync(FULLM, lq[j], 1);
        lq[j] += __shfl_xor_sync(FULLM, lq[j], 2);
    }
    if (kq == 0){
        #pragma unroll
        for (int j = 0; j < 8; j++){
            atomicAdd(&ssum[cog*8+j], ls[j]);
            atomicAdd(&ssq [cog*8+j], lq[j]);
        }
    }
    __syncthreads();
    if (t < C1){
        d_ps0[blockIdx.x*C1 + t] = ssum[t];
        d_pq0[blockIdx.x*C1 + t] = ssq[t];
    }
}

// ---------------- stats finalize ----------------
__global__ void k_stats(int which){
    const float *ps, *pq; float *mean, *istd; int nblk, C;
    if (which == 0){ ps = d_ps0; pq = d_pq0; mean = d_mean0; istd = d_istd0; nblk = 2048; C = 64; }
    else if (which == 1){ ps = d_ps1; pq = d_pq1; mean = d_mean1; istd = d_istd1; nblk = 2048; C = 64; }
    else { ps = d_ps2; pq = d_pq2; mean = d_mean2; istd = d_istd2; nblk = 4096; C = 128; }
    int c = blockIdx.x;
    __shared__ float rs[256], rq[256];
    float s = 0.f, q = 0.f;
    for (int i = threadIdx.x; i < nblk; i += 256){ s += ps[i*C + c]; q += pq[i*C + c]; }
    rs[threadIdx.x] = s; rq[threadIdx.x] = q;
    __syncthreads();
    for (int o = 128; o; o >>= 1){
        if (threadIdx.x < o){ rs[threadIdx.x] += rs[threadIdx.x+o]; rq[threadIdx.x] += rq[threadIdx.x+o]; }
        __syncthreads();
    }
    if (threadIdx.x == 0){
        float cnt = (float)(B_*S_*K_);
        float m = rs[0] / cnt;
        float v = rq[0] / cnt - m*m;
        mean[c] = m;
        istd[c] = rsqrtf(v + 1e-5f);
    }
}

// ---------------- layer1 ----------------
__global__ void __launch_bounds__(128, 4) k_g1(const float* __restrict__ W1g,
                     const float* __restrict__ g0, const float* __restrict__ b0){
    extern __shared__ float dyn[];
    float* sx = dyn;                 // 4 * C1 * ST
    float* sw = dyn + 4*C1*ST;       // C1 * 64
    __shared__ float ssum[C2], ssq[C2], sa[C1], sb[C1];
    int t = threadIdx.x;
    int bs0 = blockIdx.x*4;

    for (int e = t; e < C1*64; e += 128){
        int ci = e >> 6, co = e & 63;
        sw[e] = W1g[co*C1 + ci];
    }
    if (t < C1){
        float a = d_istd0[t]*g0[t];
        sa[t] = a;
        sb[t] = fmaf(-d_mean0[t], a, b0[t]);
        ssum[t] = 0.f; ssq[t] = 0.f;
    }
    __syncthreads();

    {
        const float4* src = (const float4*)&d_buf0[(size_t)bs0*C1*K_];
        for (int e = t; e < 2048; e += 128){
            float4 v = src[e];
            int p = e >> 9, r2 = e & 511;
            int ci = r2 >> 3, k4 = (r2 & 7)*4;
            float a = sa[ci], bb = sb[ci], r;
            r = fmaf(v.x,a,bb); v.x = r >= 0.f ? r : 0.1f*r;
            r = fmaf(v.y,a,bb); v.y = r >= 0.f ? r : 0.1f*r;
            r = fmaf(v.z,a,bb); v.z = r >= 0.f ? r : 0.1f*r;
            r = fmaf(v.w,a,bb); v.w = r >= 0.f ? r : 0.1f*r;
            *(float4*)&sx[p*C1*ST + ci*ST + k4] = v;
        }
    }
    __syncthreads();

    int lane = t & 31, wp = t >> 5;
    int kq = lane & 3, cog = lane >> 2;
    const float* xb_ = &sx[wp*C1*ST + kq*8];
    const float* wb_ = sw + cog*8;
    ull acc[8][4];
    #pragma unroll
    for (int j = 0; j < 8; j++){ acc[j][0]=0; acc[j][1]=0; acc[j][2]=0; acc[j][3]=0; }

    for (int ci = 0; ci < C1; ci++){
        float4 xa = *(const float4*)(xb_ + ci*ST);
        float4 xc = *(const float4*)(xb_ + ci*ST + 4);
        ull x0 = pk(xa.x,xa.y), x1 = pk(xa.z,xa.w);
        ull x2 = pk(xc.x,xc.y), x3 = pk(xc.z,xc.w);
        float4 wa = *(const float4*)(wb_ + ci*64);
        float4 wc = *(const float4*)(wb_ + ci*64 + 4);
        float wv[8] = {wa.x,wa.y,wa.z,wa.w, wc.x,wc.y,wc.z,wc.w};
        #pragma unroll
        for (int j = 0; j < 8; j++){
            ull w2 = pk(wv[j], wv[j]);
            acc[j][0] = fma2(w2, x0, acc[j][0]);
            acc[j][1] = fma2(w2, x1, acc[j][1]);
            acc[j][2] = fma2(w2, x2, acc[j][2]);
            acc[j][3] = fma2(w2, x3, acc[j][3]);
        }
    }

    int bs = bs0 + wp;
    float* orow = &d_buf1[(size_t)bs*C2*K_];
    float ls[8], lq[8];
    #pragma unroll
    for (int j = 0; j < 8; j++){
        float2 a0 = upk(acc[j][0]), a1 = upk(acc[j][1]);
        float2 a2 = upk(acc[j][2]), a3 = upk(acc[j][3]);
        *(float4*)&orow[(cog*8+j)*K_ + kq*8]     = make_float4(a0.x,a0.y,a1.x,a1.y);
        *(float4*)&orow[(cog*8+j)*K_ + kq*8 + 4] = make_float4(a2.x,a2.y,a3.x,a3.y);
        ls[j] = ((a0.x+a0.y)+(a1.x+a1.y)) + ((a2.x+a2.y)+(a3.x+a3.y));
        float q0 = fmaf(a0.x,a0.x, fmaf(a0.y,a0.y, fmaf(a1.x,a1.x, a1.y*a1.y)));
        lq[j] = fmaf(a2.x,a2.x, fmaf(a2.y,a2.y, fmaf(a3.x,a3.x, fmaf(a3.y,a3.y, q0))));
    }
    #pragma unroll
    for (int j = 0; j < 8; j++){
        ls[j] += __shfl_xor_sync(FULLM, ls[j], 1);
        ls[j] += __shfl_xor_sync(FULLM, ls[j], 2);
        lq[j] += __shfl_xor_sync(FULLM, lq[j], 1);
        lq[j] += __shfl_xor_sync(FULLM, lq[j], 2);
    }
    if (kq == 0){
        #pragma unroll
        for (int j = 0; j < 8; j++){
            atomicAdd(&ssum[cog*8+j], ls[j]);
            atomicAdd(&ssq [cog*8+j], lq[j]);
        }
    }
    __syncthreads();
    if (t < C2){
        d_ps1[blockIdx.x*C2 + t] = ssum[t];
        d_pq1[blockIdx.x*C2 + t] = ssq[t];
    }
}

// ---------------- layer2: 2 points/block, 2 warps/point, max/min over k ----------------
__global__ void __launch_bounds__(128, 4) k_g2(const float* __restrict__ W2g,
                     const float* __restrict__ g1, const float* __restrict__ b1){
    extern __shared__ float dyn[];
    float* sx = dyn;                 // 2 * C2 * ST
    float* sw = dyn + 2*C2*ST;       // C2 * 128
    __shared__ float sa[C2], sb[C2], ssum[C3], ssq[C3];
    int t = threadIdx.x;
    int bs0 = blockIdx.x*2;

    for (int e = t; e < C2*C3; e += 128){
        int ci = e >> 7, co = e & 127;
        sw[e] = W2g[co*C2 + ci];
    }
    if (t < C2){
        float a = d_istd1[t]*g1[t];
        sa[t] = a;
        sb[t] = fmaf(-d_mean1[t], a, b1[t]);
    }
    if (t < C3){ ssum[t] = 0.f; ssq[t] = 0.f; }
    __syncthreads();

    {
        const float4* src = (const float4*)&d_buf1[(size_t)bs0*C2*K_];
        for (int e = t; e < 1024; e += 128){
            float4 v = src[e];
            int p = e >> 9, r2 = e & 511;
            int ci = r2 >> 3, k4 = (r2 & 7)*4;
            float a = sa[ci], bb = sb[ci], r;
            r = fmaf(v.x,a,bb); v.x = r >= 0.f ? r : 0.1f*r;
            r = fmaf(v.y,a,bb); v.y = r >= 0.f ? r : 0.1f*r;
            r = fmaf(v.z,a,bb); v.z = r >= 0.f ? r : 0.1f*r;
            r = fmaf(v.w,a,bb); v.w = r >= 0.f ? r : 0.1f*r;
            *(float4*)&sx[p*C2*ST + ci*ST + k4] = v;
        }
    }
    __syncthreads();

    int lane = t & 31, wp = t >> 5;
    int pt = wp >> 1, half = wp & 1;
    int kq = lane & 3, cog = lane >> 2;
    const float* xb_ = &sx[pt*C2*ST + kq*8];
    const float* wb_ = sw + half*64 + cog*8;
    ull acc[8][4];
    #pragma unroll
    for (int j = 0; j < 8; j++){ acc[j][0]=0; acc[j][1]=0; acc[j][2]=0; acc[j][3]=0; }

    for (int ci = 0; ci < C2; ci++){
        float4 xa = *(const float4*)(xb_ + ci*ST);
        float4 xc = *(const float4*)(xb_ + ci*ST + 4);
        ull x0 = pk(xa.x,xa.y), x1 = pk(xa.z,xa.w);
        ull x2 = pk(xc.x,xc.y), x3 = pk(xc.z,xc.w);
        float4 wa = *(const float4*)(wb_ + ci*128);
        float4 wc = *(const float4*)(wb_ + ci*128 + 4);
        float wv[8] = {wa.x,wa.y,wa.z,wa.w, wc.x,wc.y,wc.z,wc.w};
        #pragma unroll
        for (int j = 0; j < 8; j++){
            ull w2 = pk(wv[j], wv[j]);
            acc[j][0] = fma2(w2, x0, acc[j][0]);
            acc[j][1] = fma2(w2, x1, acc[j][1]);
            acc[j][2] = fma2(w2, x2, acc[j][2]);
            acc[j][3] = fma2(w2, x3, acc[j][3]);
        }
    }

    int bs = bs0 + pt;
    float lmx[8], lmn[8], ls[8], lq[8];
    #pragma unroll
    for (int j = 0; j < 8; j++){
        float2 a0 = upk(acc[j][0]), a1 = upk(acc[j][1]);
        float2 a2 = upk(acc[j][2]), a3 = upk(acc[j][3]);
        lmx[j] = fmaxf(fmaxf(fmaxf(a0.x,a0.y),fmaxf(a1.x,a1.y)),
                       fmaxf(fmaxf(a2.x,a2.y),fmaxf(a3.x,a3.y)));
        lmn[j] = fminf(fminf(fminf(a0.x,a0.y),fminf(a1.x,a1.y)),
                       fminf(fminf(a2.x,a2.y),fminf(a3.x,a3.y)));
        ls[j] = ((a0.x+a0.y)+(a1.x+a1.y)) + ((a2.x+a2.y)+(a3.x+a3.y));
        float q0 = fmaf(a0.x,a0.x, fmaf(a0.y,a0.y, fmaf(a1.x,a1.x, a1.y*a1.y)));
        lq[j] = fmaf(a2.x,a2.x, fmaf(a2.y,a2.y, fmaf(a3.x,a3.x, fmaf(a3.y,a3.y, q0))));
    }
    #pragma unroll
    for (int j = 0; j < 8; j++){
        lmx[j] = fmaxf(lmx[j], __shfl_xor_sync(FULLM, lmx[j], 1));
        lmx[j] = fmaxf(lmx[j], __shfl_xor_sync(FULLM, lmx[j], 2));
        lmn[j] = fminf(lmn[j], __shfl_xor_sync(FULLM, lmn[j], 1));
        lmn[j] = fminf(lmn[j], __shfl_xor_sync(FULLM, lmn[j], 2));
        ls[j] += __shfl_xor_sync(FULLM, ls[j], 1);
        ls[j] += __shfl_xor_sync(FULLM, ls[j], 2);
        lq[j] += __shfl_xor_sync(FULLM, lq[j], 1);
        lq[j] += __shfl_xor_sync(FULLM, lq[j], 2);
    }
    if (kq == 0){
        #pragma unroll
        for (int j = 0; j < 8; j++){
            int co = half*64 + cog*8 + j;
            d_maxb[bs*C3 + co] = lmx[j];
            d_minb[bs*C3 + co] = lmn[j];
            atomicAdd(&ssum[co], ls[j]);
            atomicAdd(&ssq [co], lq[j]);
        }
    }
    __syncthreads();
    if (t < C3){
        d_ps2[blockIdx.x*C3 + t] = ssum[t];
        d_pq2[blockIdx.x*C3 + t] = ssq[t];
    }
}

// ---------------- final ----------------
__global__ void k_final(const float* __restrict__ g2, const float* __restrict__ b2,
                        float* __restrict__ out){
    int o = blockIdx.x*blockDim.x + threadIdx.x;
    if (o >= B_*C3*S_) return;
    int s  = o & (S_ - 1);
    int co = (o >> 12) & 127;
    int b  = o >> 19;
    float a = d_istd2[co]*g2[co];
    float base = fmaf(-d_mean2[co], a, b2[co]);
    int bs = b*S_ + s;
    float yv = (a > 0.f) ? d_maxb[bs*C3 + co] : ((a < 0.f) ? d_minb[bs*C3 + co] : 0.f);
    float r = fmaf(yv, a, base);
    out[B_*3*S_ + o] = r >= 0.f ? r : 0.1f*r;
}

extern "C" void kernel_launch(void* const* d_in, const int* in_sizes, int n_in,
                              void* d_out, int out_size){
    const float* xyz    = (const float*)d_in[0];
    const float* points = (const float*)d_in[1];
    const float* W0     = (const float*)d_in[2];
    const float* W1     = (const float*)d_in[3];
    const float* W2     = (const float*)d_in[4];
    const float* g0     = (const float*)d_in[5];
    const float* b0     = (const float*)d_in[6];
    const float* g1     = (const float*)d_in[7];
    const float* b1     = (const float*)d_in[8];
    const float* g2     = (const float*)d_in[9];
    const float* b2     = (const float*)d_in[10];
    float* out = (float*)d_out;

    const int smem0 = (4*C0*ST + C0*64) * 4;
    const int smem1 = (4*C1*ST + C1*64) * 4;
    const int smem2 = (2*C2*ST + C2*C3) * 4;
    cudaFuncSetAttribute(k_g0, cudaFuncAttributeMaxDynamicSharedMemorySize, smem0);
    cudaFuncSetAttribute(k_g1, cudaFuncAttributeMaxDynamicSharedMemorySize, smem1);
    cudaFuncSetAttribute(k_g2, cudaFuncAttributeMaxDynamicSharedMemorySize, smem2);

    // k_knn stays launch #4 so ncu's fixed capture slot profiles it
    k_xyz <<<(B_*N_ + 255)/256, 256>>>(xyz, out);
    k_tr  <<<dim3(N_/64, C1/32, B_), dim3(32,8)>>>(points, 0);
    k_tr  <<<dim3(N_/64, C1/32, B_), dim3(32,8)>>>(points, N_/64);
    k_knn <<<B_*S_/8, 128>>>();
    k_g0  <<<B_*S_/4, 128, smem0>>>(W0);
    k_stats<<<64, 256>>>(0);
    k_g1  <<<B_*S_/4, 128, smem1>>>(W1, g0, b0);
    k_stats<<<64, 256>>>(1);
    k_g2  <<<B_*S_/2, 128, smem2>>>(W2, g1, b1);
    k_stats<<<128, 256>>>(2);
    k_final<<<(B_*C3*S_ + 255)/256, 256>>>(g2, b2, out);
}

// round 13
// speedup vs baseline: 1.0779x; 1.0779x over previous
#include <cuda_runtime.h>

#define B_ 2
#define N_ 16384
#define S_ 4096
#define K_ 32
#define C0 67
#define C1 64
#define C2 64
#define C3 128
#define ST 36
#define FULLM 0xffffffffu
#define FINF 3.402823466e38f

typedef unsigned long long ull;

__device__ __forceinline__ ull fma2(ull a, ull b, ull c){
    ull d;
    asm("fma.rn.f32x2 %0, %1, %2, %3;" : "=l"(d) : "l"(a), "l"(b), "l"(c));
    return d;
}
__device__ __forceinline__ ull pk(float lo, float hi){
    ull r; asm("mov.b64 %0, {%1,%2};" : "=l"(r) : "f"(lo), "f"(hi)); return r;
}
__device__ __forceinline__ float2 upk(ull v){
    float2 f; asm("mov.b64 {%0,%1}, %2;" : "=f"(f.x), "=f"(f.y) : "l"(v)); return f;
}

// ---------------- scratch ----------------
__device__ __align__(16) float  d_pt[B_*N_*C1];
__device__ __align__(16) float4 d_xyz4[B_*N_];
__device__ __align__(16) float4 d_c2[B_*N_];     // (-2x,-2y,-2z,|p|^2) for KNN
__device__              int     d_knn[B_*S_*K_];
__device__ __align__(16) float  d_buf0[(size_t)B_*S_*C1*K_];
__device__ __align__(16) float  d_buf1[(size_t)B_*S_*C2*K_];
__device__              float   d_maxb[B_*S_*C3];
__device__              float   d_minb[B_*S_*C3];
__device__              float   d_ps0[4096*C1], d_pq0[4096*C1];
__device__              float   d_ps1[4096*C2], d_pq1[4096*C2];
__device__              float   d_ps2[8192*C3], d_pq2[8192*C3];
__device__              float   d_mean0[C1], d_istd0[C1];
__device__              float   d_mean1[C2], d_istd1[C2];
__device__              float   d_mean2[C3], d_istd2[C3];

// ---------------- transpose points (split-capable) ----------------
__global__ void k_tr(const float* __restrict__ pts, int xoff){
    __shared__ float tile[32][33];
    int b = blockIdx.z, c0 = blockIdx.y*32, n0 = (blockIdx.x + xoff)*32;
    for (int j = threadIdx.y; j < 32; j += 8)
        tile[j][threadIdx.x] = pts[((size_t)(b*C1 + c0 + j))*N_ + n0 + threadIdx.x];
    __syncthreads();
    for (int j = threadIdx.y; j < 32; j += 8)
        d_pt[((size_t)(b*N_ + n0 + j))*C1 + c0 + threadIdx.x] = tile[threadIdx.x][j];
}

// ---------------- xyz4 + candidate precompute + new_xyz ----------------
__global__ void k_xyz(const float* __restrict__ xyz, float* __restrict__ out){
    int i = blockIdx.x*blockDim.x + threadIdx.x;
    if (i >= B_*N_) return;
    int b = i / N_, n = i % N_;
    float x = xyz[(b*3+0)*N_+n], y = xyz[(b*3+1)*N_+n], z = xyz[(b*3+2)*N_+n];
    float w = fmaf(z,z, fmaf(y,y, x*x));
    d_xyz4[i] = make_float4(x, y, z, w);
    d_c2[i]   = make_float4(-2.0f*x, -2.0f*y, -2.0f*z, w);
    if (n < S_){
        out[(b*3+0)*S_+n] = x;
        out[(b*3+1)*S_+n] = y;
        out[(b*3+2)*S_+n] = z;
    }
}

// ---------------- KNN: 2 q/warp; double-buffered tiles; 3-fma distance ----------------
__device__ __forceinline__ void knn_group(float d, int nbase, int lane,
                                          float& bd, int& bi, float& cm){
    unsigned m = __ballot_sync(FULLM, d < cm);
    if (m){
        do {
            int src = __ffs(m) - 1; m &= m - 1;
            float cd = __shfl_sync(FULLM, d, src);
            int   cn = nbase + src;
            float pk_ = __shfl_up_sync(FULLM, bd, 1);
            int   pi_ = __shfl_up_sync(FULLM, bi, 1);
            if (lane == 0) pk_ = -FINF;
            if (bd > cd){
                bool f = (pk_ <= cd);
                bd = f ? cd : pk_;
                bi = f ? cn : pi_;
            }
        } while (m);
        cm = __shfl_sync(FULLM, bd, 31);
    }
}

__global__ void __launch_bounds__(256) k_knn(){
    __shared__ float4 tile[2][1024];
    int t = threadIdx.x;
    int lane = t & 31, w = t >> 5;
    int qg0 = (blockIdx.x*8 + w)*2;           // pair of consecutive queries
    int b = qg0 >> 12;
    int s0 = qg0 & (S_ - 1);
    const float4* base = &d_c2[b*N_];
    float4 cA = d_xyz4[b*N_ + s0], cB = d_xyz4[b*N_ + s0 + 1];
    float ax = cA.x, ay = cA.y, az = cA.z;
    float bx = cB.x, by = cB.y, bz = cB.z;

    float bd0 = FINF, bd1 = FINF;
    int   bi0 = 0,    bi1 = 0;
    float cm0 = FINF, cm1 = FINF;

    // preload tile 0
    tile[0][t]       = base[t];
    tile[0][t + 256] = base[t + 256];
    tile[0][t + 512] = base[t + 512];
    tile[0][t + 768] = base[t + 768];
    __syncthreads();

    int cur = 0;
    for (int j0 = 0; j0 < N_; j0 += 1024){
        float4 n0_, n1_, n2_, n3_;
        bool more = (j0 + 1024) < N_;
        if (more){
            const float4* nb = base + j0 + 1024;
            n0_ = nb[t]; n1_ = nb[t + 256]; n2_ = nb[t + 512]; n3_ = nb[t + 768];
        }

        const float4* tl = tile[cur];
        if (j0 == 0){
            for (int c = 0; c < 32; c++){
                float4 p = tl[c*32 + lane];
                float dA = fmaf(az,p.z, fmaf(ay,p.y, fmaf(ax,p.x, p.w)));
                float dB = fmaf(bz,p.z, fmaf(by,p.y, fmaf(bx,p.x, p.w)));
                knn_group(dA, c*32, lane, bd0, bi0, cm0);
                knn_group(dB, c*32, lane, bd1, bi1, cm1);
            }
        } else {
            for (int c = 0; c < 32; c += 4){
                float4 p0 = tl[(c+0)*32 + lane];
                float4 p1 = tl[(c+1)*32 + lane];
                float4 p2 = tl[(c+2)*32 + lane];
                float4 p3 = tl[(c+3)*32 + lane];
                float a0 = fmaf(az,p0.z, fmaf(ay,p0.y, fmaf(ax,p0.x, p0.w)));
                float a1 = fmaf(az,p1.z, fmaf(ay,p1.y, fmaf(ax,p1.x, p1.w)));
                float a2 = fmaf(az,p2.z, fmaf(ay,p2.y, fmaf(ax,p2.x, p2.w)));
                float a3 = fmaf(az,p3.z, fmaf(ay,p3.y, fmaf(ax,p3.x, p3.w)));
                float b0 = fmaf(bz,p0.z, fmaf(by,p0.y, fmaf(bx,p0.x, p0.w)));
                float b1 = fmaf(bz,p1.z, fmaf(by,p1.y, fmaf(bx,p1.x, p1.w)));
                float b2 = fmaf(bz,p2.z, fmaf(by,p2.y, fmaf(bx,p2.x, p2.w)));
                float b3 = fmaf(bz,p3.z, fmaf(by,p3.y, fmaf(bx,p3.x, p3.w)));
                float dmA = fminf(fminf(a0,a1), fminf(a2,a3));
                float dmB = fminf(fminf(b0,b1), fminf(b2,b3));
                unsigned any = __ballot_sync(FULLM, (dmA < cm0) | (dmB < cm1));
                if (any){
                    knn_group(a0, j0 + (c+0)*32, lane, bd0, bi0, cm0);
                    knn_group(a1, j0 + (c+1)*32, lane, bd0, bi0, cm0);
                    knn_group(a2, j0 + (c+2)*32, lane, bd0, bi0, cm0);
                    knn_group(a3, j0 + (c+3)*32, lane, bd0, bi0, cm0);
                    knn_group(b0, j0 + (c+0)*32, lane, bd1, bi1, cm1);
                    knn_group(b1, j0 + (c+1)*32, lane, bd1, bi1, cm1);
                    knn_group(b2, j0 + (c+2)*32, lane, bd1, bi1, cm1);
                    knn_group(b3, j0 + (c+3)*32, lane, bd1, bi1, cm1);
                }
            }
        }

        if (more){
            float4* nt = tile[cur ^ 1];
            nt[t] = n0_; nt[t + 256] = n1_; nt[t + 512] = n2_; nt[t + 768] = n3_;
        }
        __syncthreads();
        cur ^= 1;
    }
    d_knn[qg0*K_ + lane]      = bi0;
    d_knn[(qg0+1)*K_ + lane]  = bi1;
}

// ---------------- layer0: gather + GEMM, 8x8 tile per thread, warp per point ----------------
__global__ void __launch_bounds__(128, 4) k_g0(const float* __restrict__ W0g){
    extern __shared__ float dyn[];
    float* sx = dyn;                 // 4 * C0 * ST
    float* sw = dyn + 4*C0*ST;       // C0 * 64
    __shared__ float ssum[C1], ssq[C1];
    int t = threadIdx.x;
    int bs0 = blockIdx.x*4;

    for (int e = t; e < C0*64; e += 128){
        int ci = e >> 6, co = e & 63;
        sw[e] = W0g[co*C0 + ci];
    }
    if (t < C1){ ssum[t] = 0.f; ssq[t] = 0.f; }

    { // gather: 1 thread per (point, k)
        int s_l = t >> 5, k = t & 31;
        int bs = bs0 + s_l;
        int b = bs / S_, s = bs % S_;
        int idx = d_knn[bs*K_ + k];
        float* xr = &sx[s_l*C0*ST];
        float4 pc = d_xyz4[b*N_ + s];
        float4 pn = d_xyz4[b*N_ + idx];
        xr[0*ST + k] = pn.x - pc.x;
        xr[1*ST + k] = pn.y - pc.y;
        xr[2*ST + k] = pn.z - pc.z;
        const float4* prow = (const float4*)&d_pt[((size_t)(b*N_ + idx))*C1];
        #pragma unroll
        for (int q = 0; q < 16; q++){
            float4 v = prow[q];
            int c = 3 + q*4;
            xr[(c+0)*ST + k] = v.x;
            xr[(c+1)*ST + k] = v.y;
            xr[(c+2)*ST + k] = v.z;
            xr[(c+3)*ST + k] = v.w;
        }
    }
    __syncthreads();

    int lane = t & 31, wp = t >> 5;
    int kq = lane & 3, cog = lane >> 2;
    const float* xb_ = &sx[wp*C0*ST + kq*8];
    const float* wb_ = sw + cog*8;
    ull acc[8][4];
    #pragma unroll
    for (int j = 0; j < 8; j++){ acc[j][0]=0; acc[j][1]=0; acc[j][2]=0; acc[j][3]=0; }

    for (int ci = 0; ci < C0; ci++){
        float4 xa = *(const float4*)(xb_ + ci*ST);
        float4 xc = *(const float4*)(xb_ + ci*ST + 4);
        ull x0 = pk(xa.x,xa.y), x1 = pk(xa.z,xa.w);
        ull x2 = pk(xc.x,xc.y), x3 = pk(xc.z,xc.w);
        float4 wa = *(const float4*)(wb_ + ci*64);
        float4 wc = *(const float4*)(wb_ + ci*64 + 4);
        float wv[8] = {wa.x,wa.y,wa.z,wa.w, wc.x,wc.y,wc.z,wc.w};
        #pragma unroll
        for (int j = 0; j < 8; j++){
            ull w2 = pk(wv[j], wv[j]);
            acc[j][0] = fma2(w2, x0, acc[j][0]);
            acc[j][1] = fma2(w2, x1, acc[j][1]);
            acc[j][2] = fma2(w2, x2, acc[j][2]);
            acc[j][3] = fma2(w2, x3, acc[j][3]);
        }
    }

    int bs = bs0 + wp;
    float* orow = &d_buf0[(size_t)bs*C1*K_];
    float ls[8], lq[8];
    #pragma unroll
    for (int j = 0; j < 8; j++){
        float2 a0 = upk(acc[j][0]), a1 = upk(acc[j][1]);
        float2 a2 = upk(acc[j][2]), a3 = upk(acc[j][3]);
        *(float4*)&orow[(cog*8+j)*K_ + kq*8]     = make_float4(a0.x,a0.y,a1.x,a1.y);
        *(float4*)&orow[(cog*8+j)*K_ + kq*8 + 4] = make_float4(a2.x,a2.y,a3.x,a3.y);
        ls[j] = ((a0.x+a0.y)+(a1.x+a1.y)) + ((a2.x+a2.y)+(a3.x+a3.y));
        float q0 = fmaf(a0.x,a0.x, fmaf(a0.y,a0.y, fmaf(a1.x,a1.x, a1.y*a1.y)));
        lq[j] = fmaf(a2.x,a2.x, fmaf(a2.y,a2.y, fmaf(a3.x,a3.x, fmaf(a3.y,a3.y, q0))));
    }
    #pragma unroll
    for (int j = 0; j < 8; j++){
        ls[j] += __shfl_xor_sync(FULLM, ls[j], 1);
        ls[j] += __shfl_xor_sync(FULLM, ls[j], 2);
        lq[j] += __shfl_xor_sync(FULLM, lq[j], 1);
        lq[j] += __shfl_xor_sync(FULLM, lq[j], 2);
    }
    if (kq == 0){
        #pragma unroll
        for (int j = 0; j < 8; j++){
            atomicAdd(&ssum[cog*8+j], ls[j]);
            atomicAdd(&ssq [cog*8+j], lq[j]);
        }
    }
    __syncthreads();
    if (t < C1){
        d_ps0[blockIdx.x*C1 + t] = ssum[t];
        d_pq0[blockIdx.x*C1 + t] = ssq[t];
    }
}

// ---------------- stats finalize ----------------
__global__ void k_stats(int which){
    const float *ps, *pq; float *mean, *istd; int nblk, C;
    if (which == 0){ ps = d_ps0; pq = d_pq0; mean = d_mean0; istd = d_istd0; nblk = 2048; C = 64; }
    else if (which == 1){ ps = d_ps1; pq = d_pq1; mean = d_mean1; istd = d_istd1; nblk = 2048; C = 64; }
    else { ps = d_ps2; pq = d_pq2; mean = d_mean2; istd = d_istd2; nblk = 4096; C = 128; }
    int c = blockIdx.x;
    __shared__ float rs[256], rq[256];
    float s = 0.f, q = 0.f;
    for (int i = threadIdx.x; i < nblk; i += 256){ s += ps[i*C + c]; q += pq[i*C + c]; }
    rs[threadIdx.x] = s; rq[threadIdx.x] = q;
    __syncthreads();
    for (int o = 128; o; o >>= 1){
        if (threadIdx.x < o){ rs[threadIdx.x] += rs[threadIdx.x+o]; rq[threadIdx.x] += rq[threadIdx.x+o]; }
        __syncthreads();
    }
    if (threadIdx.x == 0){
        float cnt = (float)(B_*S_*K_);
        float m = rs[0] / cnt;
        float v = rq[0] / cnt - m*m;
        mean[c] = m;
        istd[c] = rsqrtf(v + 1e-5f);
    }
}

// ---------------- layer1 ----------------
__global__ void __launch_bounds__(128, 4) k_g1(const float* __restrict__ W1g,
                     const float* __restrict__ g0, const float* __restrict__ b0){
    extern __shared__ float dyn[];
    float* sx = dyn;                 // 4 * C1 * ST
    float* sw = dyn + 4*C1*ST;       // C1 * 64
    __shared__ float ssum[C2], ssq[C2], sa[C1], sb[C1];
    int t = threadIdx.x;
    int bs0 = blockIdx.x*4;

    for (int e = t; e < C1*64; e += 128){
        int ci = e >> 6, co = e & 63;
        sw[e] = W1g[co*C1 + ci];
    }
    if (t < C1){
        float a = d_istd0[t]*g0[t];
        sa[t] = a;
        sb[t] = fmaf(-d_mean0[t], a, b0[t]);
        ssum[t] = 0.f; ssq[t] = 0.f;
    }
    __syncthreads();

    {
        const float4* src = (const float4*)&d_buf0[(size_t)bs0*C1*K_];
        for (int e = t; e < 2048; e += 128){
            float4 v = src[e];
            int p = e >> 9, r2 = e & 511;
            int ci = r2 >> 3, k4 = (r2 & 7)*4;
            float a = sa[ci], bb = sb[ci], r;
            r = fmaf(v.x,a,bb); v.x = r >= 0.f ? r : 0.1f*r;
            r = fmaf(v.y,a,bb); v.y = r >= 0.f ? r : 0.1f*r;
            r = fmaf(v.z,a,bb); v.z = r >= 0.f ? r : 0.1f*r;
            r = fmaf(v.w,a,bb); v.w = r >= 0.f ? r : 0.1f*r;
            *(float4*)&sx[p*C1*ST + ci*ST + k4] = v;
        }
    }
    __syncthreads();

    int lane = t & 31, wp = t >> 5;
    int kq = lane & 3, cog = lane >> 2;
    const float* xb_ = &sx[wp*C1*ST + kq*8];
    const float* wb_ = sw + cog*8;
    ull acc[8][4];
    #pragma unroll
    for (int j = 0; j < 8; j++){ acc[j][0]=0; acc[j][1]=0; acc[j][2]=0; acc[j][3]=0; }

    for (int ci = 0; ci < C1; ci++){
        float4 xa = *(const float4*)(xb_ + ci*ST);
        float4 xc = *(const float4*)(xb_ + ci*ST + 4);
        ull x0 = pk(xa.x,xa.y), x1 = pk(xa.z,xa.w);
        ull x2 = pk(xc.x,xc.y), x3 = pk(xc.z,xc.w);
        float4 wa = *(const float4*)(wb_ + ci*64);
        float4 wc = *(const float4*)(wb_ + ci*64 + 4);
        float wv[8] = {wa.x,wa.y,wa.z,wa.w, wc.x,wc.y,wc.z,wc.w};
        #pragma unroll
        for (int j = 0; j < 8; j++){
            ull w2 = pk(wv[j], wv[j]);
            acc[j][0] = fma2(w2, x0, acc[j][0]);
            acc[j][1] = fma2(w2, x1, acc[j][1]);
            acc[j][2] = fma2(w2, x2, acc[j][2]);
            acc[j][3] = fma2(w2, x3, acc[j][3]);
        }
    }

    int bs = bs0 + wp;
    float* orow = &d_buf1[(size_t)bs*C2*K_];
    float ls[8], lq[8];
    #pragma unroll
    for (int j = 0; j < 8; j++){
        float2 a0 = upk(acc[j][0]), a1 = upk(acc[j][1]);
        float2 a2 = upk(acc[j][2]), a3 = upk(acc[j][3]);
        *(float4*)&orow[(cog*8+j)*K_ + kq*8]     = make_float4(a0.x,a0.y,a1.x,a1.y);
        *(float4*)&orow[(cog*8+j)*K_ + kq*8 + 4] = make_float4(a2.x,a2.y,a3.x,a3.y);
        ls[j] = ((a0.x+a0.y)+(a1.x+a1.y)) + ((a2.x+a2.y)+(a3.x+a3.y));
        float q0 = fmaf(a0.x,a0.x, fmaf(a0.y,a0.y, fmaf(a1.x,a1.x, a1.y*a1.y)));
        lq[j] = fmaf(a2.x,a2.x, fmaf(a2.y,a2.y, fmaf(a3.x,a3.x, fmaf(a3.y,a3.y, q0))));
    }
    #pragma unroll
    for (int j = 0; j < 8; j++){
        ls[j] += __shfl_xor_sync(FULLM, ls[j], 1);
        ls[j] += __shfl_xor_sync(FULLM, ls[j], 2);
        lq[j] += __shfl_xor_sync(FULLM, lq[j], 1);
        lq[j] += __shfl_xor_sync(FULLM, lq[j], 2);
    }
    if (kq == 0){
        #pragma unroll
        for (int j = 0; j < 8; j++){
            atomicAdd(&ssum[cog*8+j], ls[j]);
            atomicAdd(&ssq [cog*8+j], lq[j]);
        }
    }
    __syncthreads();
    if (t < C2){
        d_ps1[blockIdx.x*C2 + t] = ssum[t];
        d_pq1[blockIdx.x*C2 + t] = ssq[t];
    }
}

// ---------------- layer2: 2 points/block, 2 warps/point, max/min over k ----------------
__global__ void __launch_bounds__(128, 4) k_g2(const float* __restrict__ W2g,
                     const float* __restrict__ g1, const float* __restrict__ b1){
    extern __shared__ float dyn[];
    float* sx = dyn;                 // 2 * C2 * ST
    float* sw = dyn + 2*C2*ST;       // C2 * 128
    __shared__ float sa[C2], sb[C2], ssum[C3], ssq[C3];
    int t = threadIdx.x;
    int bs0 = blockIdx.x*2;

    for (int e = t; e < C2*C3; e += 128){
        int ci = e >> 7, co = e & 127;
        sw[e] = W2g[co*C2 + ci];
    }
    if (t < C2){
        float a = d_istd1[t]*g1[t];
        sa[t] = a;
        sb[t] = fmaf(-d_mean1[t], a, b1[t]);
    }
    if (t < C3){ ssum[t] = 0.f; ssq[t] = 0.f; }
    __syncthreads();

    {
        const float4* src = (const float4*)&d_buf1[(size_t)bs0*C2*K_];
        for (int e = t; e < 1024; e += 128){
            float4 v = src[e];
            int p = e >> 9, r2 = e & 511;
            int ci = r2 >> 3, k4 = (r2 & 7)*4;
            float a = sa[ci], bb = sb[ci], r;
            r = fmaf(v.x,a,bb); v.x = r >= 0.f ? r : 0.1f*r;
            r = fmaf(v.y,a,bb); v.y = r >= 0.f ? r : 0.1f*r;
            r = fmaf(v.z,a,bb); v.z = r >= 0.f ? r : 0.1f*r;
            r = fmaf(v.w,a,bb); v.w = r >= 0.f ? r : 0.1f*r;
            *(float4*)&sx[p*C2*ST + ci*ST + k4] = v;
        }
    }
    __syncthreads();

    int lane = t & 31, wp = t >> 5;
    int pt = wp >> 1, half = wp & 1;
    int kq = lane & 3, cog = lane >> 2;
    const float* xb_ = &sx[pt*C2*ST + kq*8];
    const float* wb_ = sw + half*64 + cog*8;
    ull acc[8][4];
    #pragma unroll
    for (int j = 0; j < 8; j++){ acc[j][0]=0; acc[j][1]=0; acc[j][2]=0; acc[j][3]=0; }

    for (int ci = 0; ci < C2; ci++){
        float4 xa = *(const float4*)(xb_ + ci*ST);
        float4 xc = *(const float4*)(xb_ + ci*ST + 4);
        ull x0 = pk(xa.x,xa.y), x1 = pk(xa.z,xa.w);
        ull x2 = pk(xc.x,xc.y), x3 = pk(xc.z,xc.w);
        float4 wa = *(const float4*)(wb_ + ci*128);
        float4 wc = *(const float4*)(wb_ + ci*128 + 4);
        float wv[8] = {wa.x,wa.y,wa.z,wa.w, wc.x,wc.y,wc.z,wc.w};
        #pragma unroll
        for (int j = 0; j < 8; j++){
            ull w2 = pk(wv[j], wv[j]);
            acc[j][0] = fma2(w2, x0, acc[j][0]);
            acc[j][1] = fma2(w2, x1, acc[j][1]);
            acc[j][2] = fma2(w2, x2, acc[j][2]);
            acc[j][3] = fma2(w2, x3, acc[j][3]);
        }
    }

    int bs = bs0 + pt;
    float lmx[8], lmn[8], ls[8], lq[8];
    #pragma unroll
    for (int j = 0; j < 8; j++){
        float2 a0 = upk(acc[j][0]), a1 = upk(acc[j][1]);
        float2 a2 = upk(acc[j][2]), a3 = upk(acc[j][3]);
        lmx[j] = fmaxf(fmaxf(fmaxf(a0.x,a0.y),fmaxf(a1.x,a1.y)),
                       fmaxf(fmaxf(a2.x,a2.y),fmaxf(a3.x,a3.y)));
        lmn[j] = fminf(fminf(fminf(a0.x,a0.y),fminf(a1.x,a1.y)),
                       fminf(fminf(a2.x,a2.y),fminf(a3.x,a3.y)));
        ls[j] = ((a0.x+a0.y)+(a1.x+a1.y)) + ((a2.x+a2.y)+(a3.x+a3.y));
        float q0 = fmaf(a0.x,a0.x, fmaf(a0.y,a0.y, fmaf(a1.x,a1.x, a1.y*a1.y)));
        lq[j] = fmaf(a2.x,a2.x, fmaf(a2.y,a2.y, fmaf(a3.x,a3.x, fmaf(a3.y,a3.y, q0))));
    }
    #pragma unroll
    for (int j = 0; j < 8; j++){
        lmx[j] = fmaxf(lmx[j], __shfl_xor_sync(FULLM, lmx[j], 1));
        lmx[j] = fmaxf(lmx[j], __shfl_xor_sync(FULLM, lmx[j], 2));
        lmn[j] = fminf(lmn[j], __shfl_xor_sync(FULLM, lmn[j], 1));
        lmn[j] = fminf(lmn[j], __shfl_xor_sync(FULLM, lmn[j], 2));
        ls[j] += __shfl_xor_sync(FULLM, ls[j], 1);
        ls[j] += __shfl_xor_sync(FULLM, ls[j], 2);
        lq[j] += __shfl_xor_sync(FULLM, lq[j], 1);
        lq[j] += __shfl_xor_sync(FULLM, lq[j], 2);
    }
    if (kq == 0){
        #pragma unroll
        for (int j = 0; j < 8; j++){
            int co = half*64 + cog*8 + j;
            d_maxb[bs*C3 + co] = lmx[j];
            d_minb[bs*C3 + co] = lmn[j];
            atomicAdd(&ssum[co], ls[j]);
            atomicAdd(&ssq [co], lq[j]);
        }
    }
    __syncthreads();
    if (t < C3){
        d_ps2[blockIdx.x*C3 + t] = ssum[t];
        d_pq2[blockIdx.x*C3 + t] = ssq[t];
    }
}

// ---------------- final ----------------
__global__ void k_final(const float* __restrict__ g2, const float* __restrict__ b2,
                        float* __restrict__ out){
    int o = blockIdx.x*blockDim.x + threadIdx.x;
    if (o >= B_*C3*S_) return;
    int s  = o & (S_ - 1);
    int co = (o >> 12) & 127;
    int b  = o >> 19;
    float a = d_istd2[co]*g2[co];
    float base = fmaf(-d_mean2[co], a, b2[co]);
    int bs = b*S_ + s;
    float yv = (a > 0.f) ? d_maxb[bs*C3 + co] : ((a < 0.f) ? d_minb[bs*C3 + co] : 0.f);
    float r = fmaf(yv, a, base);
    out[B_*3*S_ + o] = r >= 0.f ? r : 0.1f*r;
}

extern "C" void kernel_launch(void* const* d_in, const int* in_sizes, int n_in,
                              void* d_out, int out_size){
    const float* xyz    = (const float*)d_in[0];
    const float* points = (const float*)d_in[1];
    const float* W0     = (const float*)d_in[2];
    const float* W1     = (const float*)d_in[3];
    const float* W2     = (const float*)d_in[4];
    const float* g0     = (const float*)d_in[5];
    const float* b0     = (const float*)d_in[6];
    const float* g1     = (const float*)d_in[7];
    const float* b1     = (const float*)d_in[8];
    const float* g2     = (const float*)d_in[9];
    const float* b2     = (const float*)d_in[10];
    float* out = (float*)d_out;

    const int smem0 = (4*C0*ST + C0*64) * 4;
    const int smem1 = (4*C1*ST + C1*64) * 4;
    const int smem2 = (2*C2*ST + C2*C3) * 4;
    cudaFuncSetAttribute(k_g0, cudaFuncAttributeMaxDynamicSharedMemorySize, smem0);
    cudaFuncSetAttribute(k_g1, cudaFuncAttributeMaxDynamicSharedMemorySize, smem1);
    cudaFuncSetAttribute(k_g2, cudaFuncAttributeMaxDynamicSharedMemorySize, smem2);

    // k_knn stays launch #4 so ncu's fixed capture slot profiles it
    k_xyz <<<(B_*N_ + 255)/256, 256>>>(xyz, out);
    k_tr  <<<dim3(N_/64, C1/32, B_), dim3(32,8)>>>(points, 0);
    k_tr  <<<dim3(N_/64, C1/32, B_), dim3(32,8)>>>(points, N_/64);
    k_knn <<<B_*S_/16, 256>>>();
    k_g0  <<<B_*S_/4, 128, smem0>>>(W0);
    k_stats<<<64, 256>>>(0);
    k_g1  <<<B_*S_/4, 128, smem1>>>(W1, g0, b0);
    k_stats<<<64, 256>>>(1);
    k_g2  <<<B_*S_/2, 128, smem2>>>(W2, g1, b1);
    k_stats<<<128, 256>>>(2);
    k_final<<<(B_*C3*S_ + 255)/256, 256>>>(g2, b2, out);
}

// round 15
// speedup vs baseline: 1.0804x; 1.0023x over previous
#include <cuda_runtime.h>
#include <cstdint>

#define B_ 2
#define N_ 16384
#define S_ 4096
#define K_ 32
#define C0 67
#define C1 64
#define C2 64
#define C3 128
#define ST 36
#define FULLM 0xffffffffu
#define FINF 3.402823466e38f

typedef unsigned long long ull;

__device__ __forceinline__ ull fma2(ull a, ull b, ull c){
    ull d;
    asm("fma.rn.f32x2 %0, %1, %2, %3;" : "=l"(d) : "l"(a), "l"(b), "l"(c));
    return d;
}
__device__ __forceinline__ ull pk(float lo, float hi){
    ull r; asm("mov.b64 %0, {%1,%2};" : "=l"(r) : "f"(lo), "f"(hi)); return r;
}
__device__ __forceinline__ float2 upk(ull v){
    float2 f; asm("mov.b64 {%0,%1}, %2;" : "=f"(f.x), "=f"(f.y) : "l"(v)); return f;
}

// ---------------- scratch ----------------
__device__ __align__(16) float  d_pt[B_*N_*C1];
__device__ __align__(16) float4 d_xyz4[B_*N_];
__device__ __align__(16) float4 d_c2[B_*N_];     // (-2x,-2y,-2z,|p|^2) for KNN
__device__              int     d_knn[B_*S_*K_];
__device__ __align__(16) float  d_buf0[(size_t)B_*S_*C1*K_];
__device__ __align__(16) float  d_buf1[(size_t)B_*S_*C2*K_];
__device__              float   d_maxb[B_*S_*C3];
__device__              float   d_minb[B_*S_*C3];
__device__              float   d_ps0[4096*C1], d_pq0[4096*C1];
__device__              float   d_ps1[4096*C2], d_pq1[4096*C2];
__device__              float   d_ps2[8192*C3], d_pq2[8192*C3];
__device__              float   d_mean0[C1], d_istd0[C1];
__device__              float   d_mean1[C2], d_istd1[C2];
__device__              float   d_mean2[C3], d_istd2[C3];

// ---------------- transpose points (split-capable) ----------------
__global__ void k_tr(const float* __restrict__ pts, int xoff){
    __shared__ float tile[32][33];
    int b = blockIdx.z, c0 = blockIdx.y*32, n0 = (blockIdx.x + xoff)*32;
    for (int j = threadIdx.y; j < 32; j += 8)
        tile[j][threadIdx.x] = pts[((size_t)(b*C1 + c0 + j))*N_ + n0 + threadIdx.x];
    __syncthreads();
    for (int j = threadIdx.y; j < 32; j += 8)
        d_pt[((size_t)(b*N_ + n0 + j))*C1 + c0 + threadIdx.x] = tile[threadIdx.x][j];
}

// ---------------- xyz4 + candidate precompute + new_xyz ----------------
__global__ void k_xyz(const float* __restrict__ xyz, float* __restrict__ out){
    int i = blockIdx.x*blockDim.x + threadIdx.x;
    if (i >= B_*N_) return;
    int b = i / N_, n = i % N_;
    float x = xyz[(b*3+0)*N_+n], y = xyz[(b*3+1)*N_+n], z = xyz[(b*3+2)*N_+n];
    float w = fmaf(z,z, fmaf(y,y, x*x));
    d_xyz4[i] = make_float4(x, y, z, w);
    d_c2[i]   = make_float4(-2.0f*x, -2.0f*y, -2.0f*z, w);
    if (n < S_){
        out[(b*3+0)*S_+n] = x;
        out[(b*3+1)*S_+n] = y;
        out[(b*3+2)*S_+n] = z;
    }
}

// ---------------- KNN: 2 q/warp; bitonic init; double-buffered; 3-fma distance ----------------
__device__ __forceinline__ void knn_group(float d, int nbase, int lane,
                                          float& bd, int& bi, float& cm){
    unsigned m = __ballot_sync(FULLM, d < cm);
    if (m){
        do {
            int src = __ffs(m) - 1; m &= m - 1;
            float cd = __shfl_sync(FULLM, d, src);
            int   cn = nbase + src;
            float pk_ = __shfl_up_sync(FULLM, bd, 1);
            int   pi_ = __shfl_up_sync(FULLM, bi, 1);
            if (lane == 0) pk_ = -FINF;
            if (bd > cd){
                bool f = (pk_ <= cd);
                bd = f ? cd : pk_;
                bi = f ? cn : pi_;
            }
        } while (m);
        cm = __shfl_sync(FULLM, bd, 31);
    }
}

// full bitonic sort of 32 lane-resident (d, idx) pairs, ascending lexicographic
__device__ __forceinline__ void warp_sort32(float& d, int& i, int lane){
    #pragma unroll
    for (int kk = 2; kk <= 32; kk <<= 1){
        #pragma unroll
        for (int j = kk >> 1; j > 0; j >>= 1){
            float od = __shfl_xor_sync(FULLM, d, j);
            int   oi = __shfl_xor_sync(FULLM, i, j);
            bool ascBlock = ((lane & kk) == 0);
            bool lower    = ((lane & j)  == 0);
            bool keepMin  = (ascBlock == lower);
            bool less = (od < d) || (od == d && oi < i);
            bool take = keepMin ? less : !less;
            if (take){ d = od; i = oi; }
        }
    }
}

__global__ void __launch_bounds__(256) k_knn(){
    __shared__ float4 tile[2][1024];
    int t = threadIdx.x;
    int lane = t & 31, w = t >> 5;
    int qg0 = (blockIdx.x*8 + w)*2;
    int b = qg0 >> 12;
    int s0 = qg0 & (S_ - 1);
    const float4* base = &d_c2[b*N_];
    float4 cA = d_xyz4[b*N_ + s0], cB = d_xyz4[b*N_ + s0 + 1];
    float ax = cA.x, ay = cA.y, az = cA.z;
    float bx = cB.x, by = cB.y, bz = cB.z;

    float bd0, bd1;
    int   bi0, bi1;
    float cm0, cm1;

    tile[0][t]       = base[t];
    tile[0][t + 256] = base[t + 256];
    tile[0][t + 512] = base[t + 512];
    tile[0][t + 768] = base[t + 768];
    __syncthreads();

    int cur = 0;
    for (int j0 = 0; j0 < N_; j0 += 1024){
        float4 n0_, n1_, n2_, n3_;
        bool more = (j0 + 1024) < N_;
        if (more){
            const float4* nb = base + j0 + 1024;
            n0_ = nb[t]; n1_ = nb[t + 256]; n2_ = nb[t + 512]; n3_ = nb[t + 768];
        }

        const float4* tl = tile[cur];
        if (j0 == 0){
            { // group 0: initialize via bitonic sort (both queries)
                float4 p = tl[lane];
                bd0 = fmaf(az,p.z, fmaf(ay,p.y, fmaf(ax,p.x, p.w))); bi0 = lane;
                bd1 = fmaf(bz,p.z, fmaf(by,p.y, fmaf(bx,p.x, p.w))); bi1 = lane;
                warp_sort32(bd0, bi0, lane);
                warp_sort32(bd1, bi1, lane);
                cm0 = __shfl_sync(FULLM, bd0, 31);
                cm1 = __shfl_sync(FULLM, bd1, 31);
            }
            for (int c = 1; c < 4; c++){
                float4 p = tl[c*32 + lane];
                float dA = fmaf(az,p.z, fmaf(ay,p.y, fmaf(ax,p.x, p.w)));
                float dB = fmaf(bz,p.z, fmaf(by,p.y, fmaf(bx,p.x, p.w)));
                knn_group(dA, c*32, lane, bd0, bi0, cm0);
                knn_group(dB, c*32, lane, bd1, bi1, cm1);
            }
            for (int c = 4; c < 32; c += 4){
                float4 p0 = tl[(c+0)*32 + lane];
                float4 p1 = tl[(c+1)*32 + lane];
                float4 p2 = tl[(c+2)*32 + lane];
                float4 p3 = tl[(c+3)*32 + lane];
                float a0 = fmaf(az,p0.z, fmaf(ay,p0.y, fmaf(ax,p0.x, p0.w)));
                float a1 = fmaf(az,p1.z, fmaf(ay,p1.y, fmaf(ax,p1.x, p1.w)));
                float a2 = fmaf(az,p2.z, fmaf(ay,p2.y, fmaf(ax,p2.x, p2.w)));
                float a3 = fmaf(az,p3.z, fmaf(ay,p3.y, fmaf(ax,p3.x, p3.w)));
                float b0 = fmaf(bz,p0.z, fmaf(by,p0.y, fmaf(bx,p0.x, p0.w)));
                float b1 = fmaf(bz,p1.z, fmaf(by,p1.y, fmaf(bx,p1.x, p1.w)));
                float b2 = fmaf(bz,p2.z, fmaf(by,p2.y, fmaf(bx,p2.x, p2.w)));
                float b3 = fmaf(bz,p3.z, fmaf(by,p3.y, fmaf(bx,p3.x, p3.w)));
                float dmA = fminf(fminf(a0,a1), fminf(a2,a3));
                float dmB = fminf(fminf(b0,b1), fminf(b2,b3));
                unsigned any = __ballot_sync(FULLM, (dmA < cm0) | (dmB < cm1));
                if (any){
                    knn_group(a0, (c+0)*32, lane, bd0, bi0, cm0);
                    knn_group(a1, (c+1)*32, lane, bd0, bi0, cm0);
                    knn_group(a2, (c+2)*32, lane, bd0, bi0, cm0);
                    knn_group(a3, (c+3)*32, lane, bd0, bi0, cm0);
                    knn_group(b0, (c+0)*32, lane, bd1, bi1, cm1);
                    knn_group(b1, (c+1)*32, lane, bd1, bi1, cm1);
                    knn_group(b2, (c+2)*32, lane, bd1, bi1, cm1);
                    knn_group(b3, (c+3)*32, lane, bd1, bi1, cm1);
                }
            }
        } else {
            for (int c = 0; c < 32; c += 4){
                float4 p0 = tl[(c+0)*32 + lane];
                float4 p1 = tl[(c+1)*32 + lane];
                float4 p2 = tl[(c+2)*32 + lane];
                float4 p3 = tl[(c+3)*32 + lane];
                float a0 = fmaf(az,p0.z, fmaf(ay,p0.y, fmaf(ax,p0.x, p0.w)));
                float a1 = fmaf(az,p1.z, fmaf(ay,p1.y, fmaf(ax,p1.x, p1.w)));
                float a2 = fmaf(az,p2.z, fmaf(ay,p2.y, fmaf(ax,p2.x, p2.w)));
                float a3 = fmaf(az,p3.z, fmaf(ay,p3.y, fmaf(ax,p3.x, p3.w)));
                float b0 = fmaf(bz,p0.z, fmaf(by,p0.y, fmaf(bx,p0.x, p0.w)));
                float b1 = fmaf(bz,p1.z, fmaf(by,p1.y, fmaf(bx,p1.x, p1.w)));
                float b2 = fmaf(bz,p2.z, fmaf(by,p2.y, fmaf(bx,p2.x, p2.w)));
                float b3 = fmaf(bz,p3.z, fmaf(by,p3.y, fmaf(bx,p3.x, p3.w)));
                float dmA = fminf(fminf(a0,a1), fminf(a2,a3));
                float dmB = fminf(fminf(b0,b1), fminf(b2,b3));
                unsigned any = __ballot_sync(FULLM, (dmA < cm0) | (dmB < cm1));
                if (any){
                    knn_group(a0, j0 + (c+0)*32, lane, bd0, bi0, cm0);
                    knn_group(a1, j0 + (c+1)*32, lane, bd0, bi0, cm0);
                    knn_group(a2, j0 + (c+2)*32, lane, bd0, bi0, cm0);
                    knn_group(a3, j0 + (c+3)*32, lane, bd0, bi0, cm0);
                    knn_group(b0, j0 + (c+0)*32, lane, bd1, bi1, cm1);
                    knn_group(b1, j0 + (c+1)*32, lane, bd1, bi1, cm1);
                    knn_group(b2, j0 + (c+2)*32, lane, bd1, bi1, cm1);
                    knn_group(b3, j0 + (c+3)*32, lane, bd1, bi1, cm1);
                }
            }
        }

        if (more){
            float4* nt = tile[cur ^ 1];
            nt[t] = n0_; nt[t + 256] = n1_; nt[t + 512] = n2_; nt[t + 768] = n3_;
        }
        __syncthreads();
        cur ^= 1;
    }
    d_knn[qg0*K_ + lane]      = bi0;
    d_knn[(qg0+1)*K_ + lane]  = bi1;
}

// ---------------- layer0: gather + GEMM, 8x8 tile per thread, warp per point ----------------
__global__ void __launch_bounds__(128, 4) k_g0(const float* __restrict__ W0g){
    extern __shared__ float dyn[];
    float* sx = dyn;
    float* sw = dyn + 4*C0*ST;
    __shared__ float ssum[C1], ssq[C1];
    int t = threadIdx.x;
    int bs0 = blockIdx.x*4;

    for (int e = t; e < C0*64; e += 128){
        int ci = e >> 6, co = e & 63;
        sw[e] = W0g[co*C0 + ci];
    }
    if (t < C1){ ssum[t] = 0.f; ssq[t] = 0.f; }

    {
        int s_l = t >> 5, k = t & 31;
        int bs = bs0 + s_l;
        int b = bs / S_, s = bs % S_;
        int idx = d_knn[bs*K_ + k];
        float* xr = &sx[s_l*C0*ST];
        float4 pc = d_xyz4[b*N_ + s];
        float4 pn = d_xyz4[b*N_ + idx];
        xr[0*ST + k] = pn.x - pc.x;
        xr[1*ST + k] = pn.y - pc.y;
        xr[2*ST + k] = pn.z - pc.z;
        const float4* prow = (const float4*)&d_pt[((size_t)(b*N_ + idx))*C1];
        #pragma unroll
        for (int q = 0; q < 16; q++){
            float4 v = prow[q];
            int c = 3 + q*4;
            xr[(c+0)*ST + k] = v.x;
            xr[(c+1)*ST + k] = v.y;
            xr[(c+2)*ST + k] = v.z;
            xr[(c+3)*ST + k] = v.w;
        }
    }
    __syncthreads();

    int lane = t & 31, wp = t >> 5;
    int kq = lane & 3, cog = lane >> 2;
    const float* xb_ = &sx[wp*C0*ST + kq*8];
    const float* wb_ = sw + cog*8;
    ull acc[8][4];
    #pragma unroll
    for (int j = 0; j < 8; j++){ acc[j][0]=0; acc[j][1]=0; acc[j][2]=0; acc[j][3]=0; }

    for (int ci = 0; ci < C0; ci++){
        float4 xa = *(const float4*)(xb_ + ci*ST);
        float4 xc = *(const float4*)(xb_ + ci*ST + 4);
        ull x0 = pk(xa.x,xa.y), x1 = pk(xa.z,xa.w);
        ull x2 = pk(xc.x,xc.y), x3 = pk(xc.z,xc.w);
        float4 wa = *(const float4*)(wb_ + ci*64);
        float4 wc = *(const float4*)(wb_ + ci*64 + 4);
        float wv[8] = {wa.x,wa.y,wa.z,wa.w, wc.x,wc.y,wc.z,wc.w};
        #pragma unroll
        for (int j = 0; j < 8; j++){
            ull w2 = pk(wv[j], wv[j]);
            acc[j][0] = fma2(w2, x0, acc[j][0]);
            acc[j][1] = fma2(w2, x1, acc[j][1]);
            acc[j][2] = fma2(w2, x2, acc[j][2]);
            acc[j][3] = fma2(w2, x3, acc[j][3]);
        }
    }

    int bs = bs0 + wp;
    float* orow = &d_buf0[(size_t)bs*C1*K_];
    float ls[8], lq[8];
    #pragma unroll
    for (int j = 0; j < 8; j++){
        float2 a0 = upk(acc[j][0]), a1 = upk(acc[j][1]);
        float2 a2 = upk(acc[j][2]), a3 = upk(acc[j][3]);
        *(float4*)&orow[(cog*8+j)*K_ + kq*8]     = make_float4(a0.x,a0.y,a1.x,a1.y);
        *(float4*)&orow[(cog*8+j)*K_ + kq*8 + 4] = make_float4(a2.x,a2.y,a3.x,a3.y);
        ls[j] = ((a0.x+a0.y)+(a1.x+a1.y)) + ((a2.x+a2.y)+(a3.x+a3.y));
        float q0 = fmaf(a0.x,a0.x, fmaf(a0.y,a0.y, fmaf(a1.x,a1.x, a1.y*a1.y)));
        lq[j] = fmaf(a2.x,a2.x, fmaf(a2.y,a2.y, fmaf(a3.x,a3.x, fmaf(a3.y,a3.y, q0))));
    }
    #pragma unroll
    for (int j = 0; j < 8; j++){
        ls[j] += __shfl_xor_sync(FULLM, ls[j], 1);
        ls[j] += __shfl_xor_sync(FULLM, ls[j], 2);
        lq[j] += __shfl_xor_sync(FULLM, lq[j], 1);
        lq[j] += __shfl_xor_sync(FULLM, lq[j], 2);
    }
    if (kq == 0){
        #pragma unroll
        for (int j = 0; j < 8; j++){
            atomicAdd(&ssum[cog*8+j], ls[j]);
            atomicAdd(&ssq [cog*8+j], lq[j]);
        }
    }
    __syncthreads();
    if (t < C1){
        d_ps0[blockIdx.x*C1 + t] = ssum[t];
        d_pq0[blockIdx.x*C1 + t] = ssq[t];
    }
}

// ---------------- stats finalize ----------------
__global__ void k_stats(int which){
    const float *ps, *pq; float *mean, *istd; int nblk, C;
    if (which == 0){ ps = d_ps0; pq = d_pq0; mean = d_mean0; istd = d_istd0; nblk = 2048; C = 64; }
    else if (which == 1){ ps = d_ps1; pq = d_pq1; mean = d_mean1; istd = d_istd1; nblk = 2048; C = 64; }
    else { ps = d_ps2; pq = d_pq2; mean = d_mean2; istd = d_istd2; nblk = 4096; C = 128; }
    int c = blockIdx.x;
    __shared__ float rs[256], rq[256];
    float s = 0.f, q = 0.f;
    for (int i = threadIdx.x; i < nblk; i += 256){ s += ps[i*C + c]; q += pq[i*C + c]; }
    rs[threadIdx.x] = s; rq[threadIdx.x] = q;
    __syncthreads();
    for (int o = 128; o; o >>= 1){
        if (threadIdx.x < o){ rs[threadIdx.x] += rs[threadIdx.x+o]; rq[threadIdx.x] += rq[threadIdx.x+o]; }
        __syncthreads();
    }
    if (threadIdx.x == 0){
        float cnt = (float)(B_*S_*K_);
        float m = rs[0] / cnt;
        float v = rq[0] / cnt - m*m;
        mean[c] = m;
        istd[c] = rsqrtf(v + 1e-5f);
    }
}

// ---------------- layer1 ----------------
__global__ void __launch_bounds__(128, 4) k_g1(const float* __restrict__ W1g,
                     const float* __restrict__ g0, const float* __restrict__ b0){
    extern __shared__ float dyn[];
    float* sx = dyn;
    float* sw = dyn + 4*C1*ST;
    __shared__ float ssum[C2], ssq[C2], sa[C1], sb[C1];
    int t = threadIdx.x;
    int bs0 = blockIdx.x*4;

    for (int e = t; e < C1*64; e += 128){
        int ci = e >> 6, co = e & 63;
        sw[e] = W1g[co*C1 + ci];
    }
    if (t < C1){
        float a = d_istd0[t]*g0[t];
        sa[t] = a;
        sb[t] = fmaf(-d_mean0[t], a, b0[t]);
        ssum[t] = 0.f; ssq[t] = 0.f;
    }
    __syncthreads();

    {
        const float4* src = (const float4*)&d_buf0[(size_t)bs0*C1*K_];
        for (int e = t; e < 2048; e += 128){
            float4 v = src[e];
            int p = e >> 9, r2 = e & 511;
            int ci = r2 >> 3, k4 = (r2 & 7)*4;
            float a = sa[ci], bb = sb[ci], r;
            r = fmaf(v.x,a,bb); v.x = r >= 0.f ? r : 0.1f*r;
            r = fmaf(v.y,a,bb); v.y = r >= 0.f ? r : 0.1f*r;
            r = fmaf(v.z,a,bb); v.z = r >= 0.f ? r : 0.1f*r;
            r = fmaf(v.w,a,bb); v.w = r >= 0.f ? r : 0.1f*r;
            *(float4*)&sx[p*C1*ST + ci*ST + k4] = v;
        }
    }
    __syncthreads();

    int lane = t & 31, wp = t >> 5;
    int kq = lane & 3, cog = lane >> 2;
    const float* xb_ = &sx[wp*C1*ST + kq*8];
    const float* wb_ = sw + cog*8;
    ull acc[8][4];
    #pragma unroll
    for (int j = 0; j < 8; j++){ acc[j][0]=0; acc[j][1]=0; acc[j][2]=0; acc[j][3]=0; }

    for (int ci = 0; ci < C1; ci++){
        float4 xa = *(const float4*)(xb_ + ci*ST);
        float4 xc = *(const float4*)(xb_ + ci*ST + 4);
        ull x0 = pk(xa.x,xa.y), x1 = pk(xa.z,xa.w);
        ull x2 = pk(xc.x,xc.y), x3 = pk(xc.z,xc.w);
        float4 wa = *(const float4*)(wb_ + ci*64);
        float4 wc = *(const float4*)(wb_ + ci*64 + 4);
        float wv[8] = {wa.x,wa.y,wa.z,wa.w, wc.x,wc.y,wc.z,wc.w};
        #pragma unroll
        for (int j = 0; j < 8; j++){
            ull w2 = pk(wv[j], wv[j]);
            acc[j][0] = fma2(w2, x0, acc[j][0]);
            acc[j][1] = fma2(w2, x1, acc[j][1]);
            acc[j][2] = fma2(w2, x2, acc[j][2]);
            acc[j][3] = fma2(w2, x3, acc[j][3]);
        }
    }

    int bs = bs0 + wp;
    float* orow = &d_buf1[(size_t)bs*C2*K_];
    float ls[8], lq[8];
    #pragma unroll
    for (int j = 0; j < 8; j++){
        float2 a0 = upk(acc[j][0]), a1 = upk(acc[j][1]);
        float2 a2 = upk(acc[j][2]), a3 = upk(acc[j][3]);
        *(float4*)&orow[(cog*8+j)*K_ + kq*8]     = make_float4(a0.x,a0.y,a1.x,a1.y);
        *(float4*)&orow[(cog*8+j)*K_ + kq*8 + 4] = make_float4(a2.x,a2.y,a3.x,a3.y);
        ls[j] = ((a0.x+a0.y)+(a1.x+a1.y)) + ((a2.x+a2.y)+(a3.x+a3.y));
        float q0 = fmaf(a0.x,a0.x, fmaf(a0.y,a0.y, fmaf(a1.x,a1.x, a1.y*a1.y)));
        lq[j] = fmaf(a2.x,a2.x, fmaf(a2.y,a2.y, fmaf(a3.x,a3.x, fmaf(a3.y,a3.y, q0))));
    }
    #pragma unroll
    for (int j = 0; j < 8; j++){
        ls[j] += __shfl_xor_sync(FULLM, ls[j], 1);
        ls[j] += __shfl_xor_sync(FULLM, ls[j], 2);
        lq[j] += __shfl_xor_sync(FULLM, lq[j], 1);
        lq[j] += __shfl_xor_sync(FULLM, lq[j], 2);
    }
    if (kq == 0){
        #pragma unroll
        for (int j = 0; j < 8; j++){
            atomicAdd(&ssum[cog*8+j], ls[j]);
            atomicAdd(&ssq [cog*8+j], lq[j]);
        }
    }
    __syncthreads();
    if (t < C2){
        d_ps1[blockIdx.x*C2 + t] = ssum[t];
        d_pq1[blockIdx.x*C2 + t] = ssq[t];
    }
}

// ---------------- layer2: 2 points/block, 2 warps/point, max/min over k ----------------
__global__ void __launch_bounds__(128, 4) k_g2(const float* __restrict__ W2g,
                     const float* __restrict__ g1, const float* __restrict__ b1){
    extern __shared__ float dyn[];
    float* sx = dyn;
    float* sw = dyn + 2*C2*ST;
    __shared__ float sa[C2], sb[C2], ssum[C3], ssq[C3];
    int t = threadIdx.x;
    int bs0 = blockIdx.x*2;

    for (int e = t; e < C2*C3; e += 128){
        int ci = e >> 7, co = e & 127;
        sw[e] = W2g[co*C2 + ci];
    }
    if (t < C2){
        float a = d_istd1[t]*g1[t];
        sa[t] = a;
        sb[t] = fmaf(-d_mean1[t], a, b1[t]);
    }
    if (t < C3){ ssum[t] = 0.f; ssq[t] = 0.f; }
    __syncthreads();

    {
        const float4* src = (const float4*)&d_buf1[(size_t)bs0*C2*K_];
        for (int e = t; e < 1024; e += 128){
            float4 v = src[e];
            int p = e >> 9, r2 = e & 511;
            int ci = r2 >> 3, k4 = (r2 & 7)*4;
            float a = sa[ci], bb = sb[ci], r;
            r = fmaf(v.x,a,bb); v.x = r >= 0.f ? r : 0.1f*r;
            r = fmaf(v.y,a,bb); v.y = r >= 0.f ? r : 0.1f*r;
            r = fmaf(v.z,a,bb); v.z = r >= 0.f ? r : 0.1f*r;
            r = fmaf(v.w,a,bb); v.w = r >= 0.f ? r : 0.1f*r;
            *(float4*)&sx[p*C2*ST + ci*ST + k4] = v;
        }
    }
    __syncthreads();

    int lane = t & 31, wp = t >> 5;
    int pt = wp >> 1, half = wp & 1;
    int kq = lane & 3, cog = lane >> 2;
    const float* xb_ = &sx[pt*C2*ST + kq*8];
    const float* wb_ = sw + half*64 + cog*8;
    ull acc[8][4];
    #pragma unroll
    for (int j = 0; j < 8; j++){ acc[j][0]=0; acc[j][1]=0; acc[j][2]=0; acc[j][3]=0; }

    for (int ci = 0; ci < C2; ci++){
        float4 xa = *(const float4*)(xb_ + ci*ST);
        float4 xc = *(const float4*)(xb_ + ci*ST + 4);
        ull x0 = pk(xa.x,xa.y), x1 = pk(xa.z,xa.w);
        ull x2 = pk(xc.x,xc.y), x3 = pk(xc.z,xc.w);
        float4 wa = *(const float4*)(wb_ + ci*128);
        float4 wc = *(const float4*)(wb_ + ci*128 + 4);
        float wv[8] = {wa.x,wa.y,wa.z,wa.w, wc.x,wc.y,wc.z,wc.w};
        #pragma unroll
        for (int j = 0; j < 8; j++){
            ull w2 = pk(wv[j], wv[j]);
            acc[j][0] = fma2(w2, x0, acc[j][0]);
            acc[j][1] = fma2(w2, x1, acc[j][1]);
            acc[j][2] = fma2(w2, x2, acc[j][2]);
            acc[j][3] = fma2(w2, x3, acc[j][3]);
        }
    }

    int bs = bs0 + pt;
    float lmx[8], lmn[8], ls[8], lq[8];
    #pragma unroll
    for (int j = 0; j < 8; j++){
        float2 a0 = upk(acc[j][0]), a1 = upk(acc[j][1]);
        float2 a2 = upk(acc[j][2]), a3 = upk(acc[j][3]);
        lmx[j] = fmaxf(fmaxf(fmaxf(a0.x,a0.y),fmaxf(a1.x,a1.y)),
                       fmaxf(fmaxf(a2.x,a2.y),fmaxf(a3.x,a3.y)));
        lmn[j] = fminf(fminf(fminf(a0.x,a0.y),fminf(a1.x,a1.y)),
                       fminf(fminf(a2.x,a2.y),fminf(a3.x,a3.y)));
        ls[j] = ((a0.x+a0.y)+(a1.x+a1.y)) + ((a2.x+a2.y)+(a3.x+a3.y));
        float q0 = fmaf(a0.x,a0.x, fmaf(a0.y,a0.y, fmaf(a1.x,a1.x, a1.y*a1.y)));
        lq[j] = fmaf(a2.x,a2.x, fmaf(a2.y,a2.y, fmaf(a3.x,a3.x, fmaf(a3.y,a3.y, q0))));
    }
    #pragma unroll
    for (int j = 0; j < 8; j++){
        lmx[j] = fmaxf(lmx[j], __shfl_xor_sync(FULLM, lmx[j], 1));
        lmx[j] = fmaxf(lmx[j], __shfl_xor_sync(FULLM, lmx[j], 2));
        lmn[j] = fminf(lmn[j], __shfl_xor_sync(FULLM, lmn[j], 1));
        lmn[j] = fminf(lmn[j], __shfl_xor_sync(FULLM, lmn[j], 2));
        ls[j] += __shfl_xor_sync(FULLM, ls[j], 1);
        ls[j] += __shfl_xor_sync(FULLM, ls[j], 2);
        lq[j] += __shfl_xor_sync(FULLM, lq[j], 1);
        lq[j] += __shfl_xor_sync(FULLM, lq[j], 2);
    }
    if (kq == 0){
        #pragma unroll
        for (int j = 0; j < 8; j++){
            int co = half*64 + cog*8 + j;
            d_maxb[bs*C3 + co] = lmx[j];
            d_minb[bs*C3 + co] = lmn[j];
            atomicAdd(&ssum[co], ls[j]);
            atomicAdd(&ssq [co], lq[j]);
        }
    }
    __syncthreads();
    if (t < C3){
        d_ps2[blockIdx.x*C3 + t] = ssum[t];
        d_pq2[blockIdx.x*C3 + t] = ssq[t];
    }
}

// ---------------- final ----------------
__global__ void k_final(const float* __restrict__ g2, const float* __restrict__ b2,
                        float* __restrict__ out){
    int o = blockIdx.x*blockDim.x + threadIdx.x;
    if (o >= B_*C3*S_) return;
    int s  = o & (S_ - 1);
    int co = (o >> 12) & 127;
    int b  = o >> 19;
    float a = d_istd2[co]*g2[co];
    float base = fmaf(-d_mean2[co], a, b2[co]);
    int bs = b*S_ + s;
    float yv = (a > 0.f) ? d_maxb[bs*C3 + co] : ((a < 0.f) ? d_minb[bs*C3 + co] : 0.f);
    float r = fmaf(yv, a, base);
    out[B_*3*S_ + o] = r >= 0.f ? r : 0.1f*r;
}

extern "C" void kernel_launch(void* const* d_in, const int* in_sizes, int n_in,
                              void* d_out, int out_size){
    const float* xyz    = (const float*)d_in[0];
    const float* points = (const float*)d_in[1];
    const float* W0     = (const float*)d_in[2];
    const float* W1     = (const float*)d_in[3];
    const float* W2     = (const float*)d_in[4];
    const float* g0     = (const float*)d_in[5];
    const float* b0     = (const float*)d_in[6];
    const float* g1     = (const float*)d_in[7];
    const float* b1     = (const float*)d_in[8];
    const float* g2     = (const float*)d_in[9];
    const float* b2     = (const float*)d_in[10];
    float* out = (float*)d_out;

    const int smem0 = (4*C0*ST + C0*64) * 4;
    const int smem1 = (4*C1*ST + C1*64) * 4;
    const int smem2 = (2*C2*ST + C2*C3) * 4;
    cudaFuncSetAttribute(k_g0, cudaFuncAttributeMaxDynamicSharedMemorySize, smem0);
    cudaFuncSetAttribute(k_g1, cudaFuncAttributeMaxDynamicSharedMemorySize, smem1);
    cudaFuncSetAttribute(k_g2, cudaFuncAttributeMaxDynamicSharedMemorySize, smem2);

    // k_knn stays launch #4 so ncu's fixed capture slot profiles it
    k_xyz <<<(B_*N_ + 255)/256, 256>>>(xyz, out);
    k_tr  <<<dim3(N_/64, C1/32, B_), dim3(32,8)>>>(points, 0);
    k_tr  <<<dim3(N_/64, C1/32, B_), dim3(32,8)>>>(points, N_/64);
    k_knn <<<B_*S_/16, 256>>>();
    k_g0  <<<B_*S_/4, 128, smem0>>>(W0);
    k_stats<<<64, 256>>>(0);
    k_g1  <<<B_*S_/4, 128, smem1>>>(W1, g0, b0);
    k_stats<<<64, 256>>>(1);
    k_g2  <<<B_*S_/2, 128, smem2>>>(W2, g1, b1);
    k_stats<<<128, 256>>>(2);
    k_final<<<(B_*C3*S_ + 255)/256, 256>>>(g2, b2, out);
}